// round 11
// baseline (speedup 1.0000x reference)
#include <cuda_runtime.h>

// CrossAttentionConditionInjection — analytic collapse, 3 kernels,
// BARRIER-FREE read overlap via L2 warming. (R11 = R10 with the warm-path
// OOB fixed: warm stream is 1024 warps for Wo's 1024 rows, not 2048.)
//
// K/V come from one condition token broadcast across seq: every score row is
// constant => softmax weights are exactly 1/S (S=2048, pow2) => attn == v1.
//   out[b,s,:] = Wo @ (Wv @ cond[b] + bv) + bo   (same vector for every s)
//
// Experiment: 12.288us floor == two SERIAL 4MB weight reads @ ~750GB/s cap.
// Wo doesn't depend on v1 -> K1 runs both reads concurrently (mv blocks +
// __ldcg warm blocks); K2 then reads Wo as L2 hits.

#define BDIM 1024   // D
#define NB   2      // B
#define NS   2048   // S

__device__ float g_v1[NB * BDIM];
__device__ float g_o1[NB * BDIM];
__device__ float g_sink;            // DCE-blocker for the L2 warm stream

// ---------------------------------------------------------------------------
// Warp-per-row matvec body (proven R7 form): y[b*D+d] = W[d,:].x[b,:] + bias.
// ---------------------------------------------------------------------------
__device__ __forceinline__ void mv_row(const float* __restrict__ W,
                                       const float* __restrict__ x,
                                       const float* __restrict__ bias,
                                       float* __restrict__ y,
                                       int w, int lane) {
    int b = w >> 10;
    int d = w & (BDIM - 1);
    const float4* W4 = reinterpret_cast<const float4*>(W + (size_t)d * BDIM);
    const float4* x4 = reinterpret_cast<const float4*>(x + (size_t)b * BDIM);
    float sum = 0.f;
#pragma unroll
    for (int i = 0; i < 8; ++i) {
        float4 wv = W4[lane + i * 32];
        float4 xv = x4[lane + i * 32];
        sum += wv.x * xv.x + wv.y * xv.y + wv.z * xv.z + wv.w * xv.w;
    }
#pragma unroll
    for (int off = 16; off; off >>= 1)
        sum += __shfl_xor_sync(0xffffffffu, sum, off);
    if (lane == 0) y[w] = sum + bias[d];
}

// ---------------------------------------------------------------------------
// K1: 384 blocks x 256 thr.
//   Blocks [0,256):   v1 matvec, 2048 warps (output rows 0..2047).
//   Blocks [256,384): warm Wo into L2, 1024 warps x one 4KB row each
//                     (rows 0..1023 — exactly covers the 4MB of Wo).
// Both 4MB read streams are concurrently in flight; no barrier anywhere.
// ---------------------------------------------------------------------------
__global__ void __launch_bounds__(256)
k1_mv1_and_warm(const float* __restrict__ Wv, const float* __restrict__ cond,
                const float* __restrict__ bv, const float* __restrict__ Wo) {
    int lane = threadIdx.x & 31;
    if (blockIdx.x < 256) {
        int w = (blockIdx.x * 256 + threadIdx.x) >> 5;          // 0..2047
        mv_row(Wv, cond, bv, g_v1, w, lane);
    } else {
        int r = ((blockIdx.x - 256) * 256 + threadIdx.x) >> 5;  // 0..1023
        const float4* W4 = reinterpret_cast<const float4*>(Wo)
                           + (size_t)r * (BDIM / 4);            // row r, in-bounds
        float acc = 0.f;
#pragma unroll
        for (int i = 0; i < 8; ++i) {
            float4 v = __ldcg(W4 + lane + i * 32);              // fill L2
            acc += v.x + v.y + v.z + v.w;
        }
        if (acc == 1.0e30f) g_sink = acc;                       // never true; no DCE
    }
}

// K2: o1 = Wo @ v1 + bo. Wo rows now L2-hit (warmed by K1); v1 is 8KB L2-hot.
__global__ void __launch_bounds__(256)
k2_mv2(const float* __restrict__ Wo, const float* __restrict__ bo) {
    int w    = (blockIdx.x * 256 + threadIdx.x) >> 5;           // 0..2047
    int lane = threadIdx.x & 31;
    mv_row(Wo, g_v1, bo, g_o1, w, lane);
}

// K3: out[b,s,:] = o1[b,:]. Coalesced float4 streaming stores (evict-first).
__global__ void __launch_bounds__(512)
k3_bcast(float4* __restrict__ out) {
    const float4* o1 = reinterpret_cast<const float4*>(g_o1);
    int i  = blockIdx.x * blockDim.x + threadIdx.x;
    int b  = i >> 19;          // / (S*D/4)
    int d4 = i & 255;          // % (D/4)
    __stcs(out + i, o1[(b << 8) + d4]);
}

extern "C" void kernel_launch(void* const* d_in, const int* in_sizes, int n_in,
                              void* d_out, int out_size) {
    // metadata order: hidden_states, condition, Wq, bq, Wk, bk, Wv, bv, Wo, bo
    const float* cond = (const float*)d_in[1];
    const float* Wv   = (const float*)d_in[6];
    const float* bv   = (const float*)d_in[7];
    const float* Wo   = (const float*)d_in[8];
    const float* bo   = (const float*)d_in[9];

    k1_mv1_and_warm<<<384, 256>>>(Wv, cond, bv, Wo);
    k2_mv2<<<256, 256>>>(Wo, bo);
    k3_bcast<<<(NB * NS * BDIM / 4) / 512, 512>>>((float4*)d_out);
}